// round 15
// baseline (speedup 1.0000x reference)
#include <cuda_runtime.h>
#include <cstdint>
#include <cstddef>

#define Bc 32
#define Tc 4096
#define Dc 128
#define CHUNKS 16
#define NBLK (Bc * CHUNKS)      // 512
#define ROWS (Tc / CHUNKS)      // 256 rows per block
#define SROWS 16                // rows per pipeline stage
#define NST (ROWS / SROWS)      // 16 stages
#define NBUF 3
#define STAGE_BYTES (SROWS * Dc * 4)   // 8192 B per tensor per stage
#define SMEM_BYTES (6 * STAGE_BYTES + 3 * 8 + 8)
#define NEG_FILL (-1e30f)
#define ALPHA 0.5f

// Scratch. g_bmax keys: zero-init == minimal key (identity for max); finalizer
// resets to 0 each launch -> graph-replay safe, order-independent -> deterministic.
__device__ unsigned g_bmax[Bc * 4 * Dc];   // [b][stat][d] monotonic keys; 64 KB
__device__ float    g_csum[NBLK];
__device__ unsigned g_count;               // zero-init; reset by finalizer

// monotonic float<->uint keys: enc preserves order; key 0 < enc(any finite)
__device__ __forceinline__ unsigned enc(float f) {
    unsigned b = __float_as_uint(f);
    return (b & 0x80000000u) ? ~b : (b | 0x80000000u);
}
__device__ __forceinline__ float dec(unsigned k) {
    if (k == 0u) return NEG_FILL;   // untouched slot (defensive; never hit)
    return (k & 0x80000000u) ? __uint_as_float(k ^ 0x80000000u)
                             : __uint_as_float(~k);
}

// lengths may arrive as int64 (declared) or int32 (JAX x64 disabled).
__device__ __forceinline__ long long read_len(const void* lp, int b) {
    const long long* p64 = (const long long*)lp;
    bool is64 = true;
#pragma unroll
    for (int i = 0; i < 16; i++) {          // first 128B, safe for both layouts
        long long v = p64[i];
        if (v < 0 || v >= (1LL << 31)) is64 = false;
    }
    if (is64) return p64[b];
    return (long long)((const int*)lp)[b];
}

__device__ __forceinline__ float4 max4(float4 a, float4 b) {
    float4 r;
    r.x = fmaxf(a.x, b.x); r.y = fmaxf(a.y, b.y);
    r.z = fmaxf(a.z, b.z); r.w = fmaxf(a.w, b.w);
    return r;
}

// ---- mbarrier / bulk-copy helpers --------------------------------------
__device__ __forceinline__ uint32_t s2u(const void* p) {
    return (uint32_t)__cvta_generic_to_shared(p);
}
__device__ __forceinline__ void mbar_init(uint32_t a, unsigned cnt) {
    asm volatile("mbarrier.init.shared::cta.b64 [%0], %1;" :: "r"(a), "r"(cnt) : "memory");
}
__device__ __forceinline__ void mbar_expect(uint32_t a, uint32_t tx) {
    asm volatile("mbarrier.arrive.expect_tx.shared::cta.b64 _, [%0], %1;"
                 :: "r"(a), "r"(tx) : "memory");
}
__device__ __forceinline__ void bulk_g2s(uint32_t dst, const void* src,
                                         uint32_t bytes, uint32_t bar) {
    asm volatile("cp.async.bulk.shared::cta.global.mbarrier::complete_tx::bytes "
                 "[%0], [%1], %2, [%3];"
                 :: "r"(dst), "l"(src), "r"(bytes), "r"(bar) : "memory");
}
__device__ __forceinline__ void mbar_wait(uint32_t a, uint32_t parity) {
    asm volatile(
        "{\n\t.reg .pred P;\n"
        "W_%=:\n\t"
        "mbarrier.try_wait.parity.acquire.cta.shared::cta.b64 P, [%0], %1, 0x989680;\n\t"
        "@P bra D_%=;\n\t"
        "bra W_%=;\n"
        "D_%=:\n\t}"
        :: "r"(a), "r"(parity) : "memory");
}
// ------------------------------------------------------------------------

__global__ __launch_bounds__(256) void seg_k1(
    const float* __restrict__ O, const float* __restrict__ Lb,
    const void* __restrict__ lens, float* __restrict__ out)
{
    extern __shared__ __align__(16) unsigned char dsm[];
    float* bufO = (float*)dsm;                                    // [NBUF][SROWS*Dc]
    float* bufL = (float*)(dsm + NBUF * STAGE_BYTES);             // [NBUF][SROWS*Dc]
    unsigned long long* bar_s = (unsigned long long*)(dsm + 2 * NBUF * STAGE_BYTES);
    int* s_flags = (int*)(dsm + 2 * NBUF * STAGE_BYTES + NBUF * 8);

    const int b   = blockIdx.y;
    const int c   = blockIdx.x;
    const int tid = threadIdx.x;
    const int col4 = tid & 31;   // d-group of 4 floats
    const int rg   = tid >> 5;   // 0..7; whole warp shares one row -> uniform masks

    const long long len  = read_len(lens, b);
    const long long half = len >> 1;
    const int t0 = c * ROWS;

    const char* gO = (const char*)(O  + ((size_t)b * Tc + t0) * Dc);
    const char* gL = (const char*)(Lb + ((size_t)b * Tc + t0) * Dc);

    uint32_t bar[NBUF], dO[NBUF], dL[NBUF];
#pragma unroll
    for (int k = 0; k < NBUF; k++) {
        bar[k] = s2u(&bar_s[k]);
        dO[k]  = s2u(bufO + k * (SROWS * Dc));
        dL[k]  = s2u(bufL + k * (SROWS * Dc));
    }

    if (tid == 0) {
#pragma unroll
        for (int k = 0; k < NBUF; k++) mbar_init(bar[k], 1);
    }
    __syncthreads();

    // Prologue: prefetch stages 0 and 1
    if (tid == 0) {
#pragma unroll
        for (int s = 0; s < 2; s++) {
            mbar_expect(bar[s], 2 * STAGE_BYTES);
            bulk_g2s(dO[s], gO + (size_t)s * STAGE_BYTES, STAGE_BYTES, bar[s]);
            bulk_g2s(dL[s], gL + (size_t)s * STAGE_BYTES, STAGE_BYTES, bar[s]);
        }
    }

    float4 mOF = {NEG_FILL, NEG_FILL, NEG_FILL, NEG_FILL};
    float4 mLF = mOF, mOS = mOF, mLS = mOF;
    float sum = 0.0f;

#pragma unroll
    for (int s = 0; s < NST; s++) {
        const int k = s % NBUF;
        mbar_wait(bar[k], (s / NBUF) & 1);

        // Early refill: buffer (s+2)%NBUF freed by stage s-1's sync.
        if (s + 2 < NST && tid == 0) {
            const int k2 = (s + 2) % NBUF;
            const size_t off = (size_t)(s + 2) * STAGE_BYTES;
            mbar_expect(bar[k2], 2 * STAGE_BYTES);
            bulk_g2s(dO[k2], gO + off, STAGE_BYTES, bar[k2]);
            bulk_g2s(dL[k2], gL + off, STAGE_BYTES, bar[k2]);
        }

        const float4* pO = (const float4*)(bufO + k * (SROWS * Dc));
        const float4* pL = (const float4*)(bufL + k * (SROWS * Dc));
#pragma unroll
        for (int rr = 0; rr < 2; rr++) {
            const int r = rg + rr * 8;            // 0..15 within stage
            float4 o = pO[r * 32 + col4];
            float4 l = pL[r * 32 + col4];
            float dx = o.x - l.x, dy = o.y - l.y, dz = o.z - l.z, dw = o.w - l.w;
            sum += dx * dx + dy * dy + dz * dz + dw * dw;
            long long t = (long long)(t0 + s * SROWS + r);
            if (t < half) {                        // warp-uniform
                mOF = max4(mOF, o); mLF = max4(mLF, l);
            } else if (t < len) {
                mOS = max4(mOS, o); mLS = max4(mLS, l);
            }
        }
        __syncthreads();                           // buffer k free for reuse
    }

    // ---- intra-block reduction, then push straight to global atomic maxes ----
    float4* red = (float4*)bufO;        // [stat][rg][col4] = 16 KB
    float*  ss  = bufL;                 // [0..255]
    red[(0 * 8 + rg) * 32 + col4] = mOF;
    red[(1 * 8 + rg) * 32 + col4] = mLF;
    red[(2 * 8 + rg) * 32 + col4] = mOS;
    red[(3 * 8 + rg) * 32 + col4] = mLS;
    ss[tid] = sum;
    __syncthreads();

    if (tid < 32) {
#pragma unroll
        for (int stat = 0; stat < 4; stat++) {
            float4 m = red[(stat * 8 + 0) * 32 + tid];
#pragma unroll
            for (int r = 1; r < 8; r++)
                m = max4(m, red[(stat * 8 + r) * 32 + tid]);
            unsigned* dst = g_bmax + (size_t)(b * 4 + stat) * Dc + tid * 4;
            atomicMax(dst + 0, enc(m.x));
            atomicMax(dst + 1, enc(m.y));
            atomicMax(dst + 2, enc(m.z));
            atomicMax(dst + 3, enc(m.w));
        }
    }
    for (int s = 128; s > 0; s >>= 1) {
        if (tid < s) ss[tid] += ss[tid + s];
        __syncthreads();
    }
    if (tid == 0) g_csum[b * CHUNKS + c] = ss[0];

    // Single global election: last of 512 blocks finalizes everything.
    if (tid < 32) __threadfence();      // covers this block's atomics + csum (tid0)
    __syncthreads();
    if (tid == 0) {
        unsigned old = atomicAdd(&g_count, 1u);
        s_flags[0] = (old == NBLK - 1) ? 1 : 0;
    }
    __syncthreads();
    if (!s_flags[0]) return;

    // ================= finalize (one block, 256 threads) =================
    __threadfence();                    // acquire side
    float*  sm1 = (float*)dsm;                       // [32][128] 16 KB
    float*  sm2 = (float*)(dsm + 16384);             // [32][128] 16 KB
    double* sd  = (double*)(dsm + 32768);            // [256] 2 KB
    float*  sbc = (float*)(dsm + 34816);             // [32]

    // 16 independent items per thread -> one L2 round-trip for all 64 KB of keys.
#pragma unroll
    for (int it = 0; it < 16; it++) {
        const int item = tid + it * 256;             // 0..4095
        const int bb = item >> 7, dd = item & 127;
        const unsigned* base = g_bmax + (size_t)(bb * 4) * Dc + dd;
        float vOF = dec(__ldcg(base + 0 * Dc));
        float vLF = dec(__ldcg(base + 1 * Dc));
        float vOS = dec(__ldcg(base + 2 * Dc));
        float vLS = dec(__ldcg(base + 3 * Dc));
        float d1 = vOF - vLF;    // empty segment: NEG-NEG = 0, matches reference
        float d2 = vOS - vLS;
        sm1[item] = d1 * d1;
        sm2[item] = d2 * d2;
    }
    {
        double dsum = (double)__ldcg(g_csum + tid) + (double)__ldcg(g_csum + tid + 256);
        sd[tid] = dsum;
    }
    __syncthreads();

    // Reset scratch for next replay (reads above complete at the sync).
#pragma unroll
    for (int i = 0; i < (Bc * 4 * Dc) / 256; i++)
        g_bmax[tid + i * 256] = 0u;
    if (tid == 0) g_count = 0u;

    // Per-b reduce over d: warp w handles b = w*4..w*4+3.
    {
        const int w = tid >> 5, l = tid & 31;
#pragma unroll
        for (int j = 0; j < 4; j++) {
            const int bb = w * 4 + j;
            float a1 = sm1[bb * 128 + l] + sm1[bb * 128 + l + 32]
                     + sm1[bb * 128 + l + 64] + sm1[bb * 128 + l + 96];
            float a2 = sm2[bb * 128 + l] + sm2[bb * 128 + l + 32]
                     + sm2[bb * 128 + l + 64] + sm2[bb * 128 + l + 96];
#pragma unroll
            for (int o = 16; o > 0; o >>= 1) {
                a1 += __shfl_down_sync(0xFFFFFFFFu, a1, o);
                a2 += __shfl_down_sync(0xFFFFFFFFu, a2, o);
            }
            if (l == 0) {
                long long lb = read_len(lens, bb);
                float valid = (lb >= 2) ? 1.0f : 0.0f;
                sbc[bb] = valid * ((a1 + a2) / (float)Dc);
            }
        }
    }
    __syncthreads();

    for (int s = 128; s > 0; s >>= 1) {
        if (tid < s) sd[tid] += sd[tid + s];
        __syncthreads();
    }

    if (tid < 32) {
        float r = sbc[tid];
#pragma unroll
        for (int o = 16; o > 0; o >>= 1)
            r += __shfl_down_sync(0xFFFFFFFFu, r, o);
        if (tid == 0) {
            double base = sd[0] / (double)((size_t)Bc * Tc * Dc);
            out[0] = (float)(base + (double)ALPHA * ((double)r / (double)Bc));
        }
    }
}

extern "C" void kernel_launch(void* const* d_in, const int* in_sizes, int n_in,
                              void* d_out, int out_size)
{
    const float* outputs = (const float*)d_in[0];
    const float* labels  = (const float*)d_in[1];
    const void*  lens    = d_in[2];
    float* out = (float*)d_out;

    cudaFuncSetAttribute(seg_k1, cudaFuncAttributeMaxDynamicSharedMemorySize, SMEM_BYTES);
    dim3 g1(CHUNKS, Bc);
    seg_k1<<<g1, 256, SMEM_BYTES>>>(outputs, labels, lens, out);
}

// round 16
// speedup vs baseline: 1.9722x; 1.9722x over previous
#include <cuda_runtime.h>
#include <cstdint>
#include <cstddef>

#define Bc 32
#define Tc 4096
#define Dc 128
#define CHUNKS 16
#define ROWS (Tc / CHUNKS)      // 256 rows per block
#define SROWS 16                // rows per pipeline stage
#define NST (ROWS / SROWS)      // 16 stages
#define NBUF 3
#define STAGE_BYTES (SROWS * Dc * 4)   // 8192 B per stage (O only)
#define OFF_BARS (NBUF * STAGE_BYTES)          // 24576
#define OFF_FLAGS (OFF_BARS + NBUF * 8)        // 24600
#define SMEM_BYTES (OFF_FLAGS + 8)             // 24608
#define NEG_FILL (-1e30f)
#define ALPHA 0.5f

// Scratch: fully overwritten (or counter-reset) every launch -> graph-safe.
__device__ float g_part[Bc * CHUNKS * 4 * Dc];  // [b][chunk][stat][d]; 1 MB
__device__ float g_csum[Bc * CHUNKS];
__device__ float g_bsum[Bc];
__device__ float g_bres1[Bc];
__device__ float g_bres2[Bc];
__device__ unsigned g_bcount[Bc];   // zero-init; reset by per-b electee
__device__ unsigned g_count;        // zero-init; reset by global electee

// lengths may arrive as int64 (declared) or int32 (JAX x64 disabled).
__device__ __forceinline__ long long read_len(const void* lp, int b) {
    const long long* p64 = (const long long*)lp;
    bool is64 = true;
#pragma unroll
    for (int i = 0; i < 16; i++) {          // first 128B, safe for both layouts
        long long v = p64[i];
        if (v < 0 || v >= (1LL << 31)) is64 = false;
    }
    if (is64) return p64[b];
    return (long long)((const int*)lp)[b];
}

__device__ __forceinline__ float4 max4(float4 a, float4 b) {
    float4 r;
    r.x = fmaxf(a.x, b.x); r.y = fmaxf(a.y, b.y);
    r.z = fmaxf(a.z, b.z); r.w = fmaxf(a.w, b.w);
    return r;
}

// Streaming (evict-first) float4 load for the LDG path.
__device__ __forceinline__ float4 ldcs4(const float4* p) {
    float4 v;
    asm volatile("ld.global.cs.v4.f32 {%0,%1,%2,%3}, [%4];"
                 : "=f"(v.x), "=f"(v.y), "=f"(v.z), "=f"(v.w)
                 : "l"(p));
    return v;
}

// ---- mbarrier / bulk-copy helpers --------------------------------------
__device__ __forceinline__ uint32_t s2u(const void* p) {
    return (uint32_t)__cvta_generic_to_shared(p);
}
__device__ __forceinline__ void mbar_init(uint32_t a, unsigned cnt) {
    asm volatile("mbarrier.init.shared::cta.b64 [%0], %1;" :: "r"(a), "r"(cnt) : "memory");
}
__device__ __forceinline__ void mbar_expect(uint32_t a, uint32_t tx) {
    asm volatile("mbarrier.arrive.expect_tx.shared::cta.b64 _, [%0], %1;"
                 :: "r"(a), "r"(tx) : "memory");
}
__device__ __forceinline__ void bulk_g2s(uint32_t dst, const void* src,
                                         uint32_t bytes, uint32_t bar) {
    asm volatile("cp.async.bulk.shared::cta.global.mbarrier::complete_tx::bytes "
                 "[%0], [%1], %2, [%3];"
                 :: "r"(dst), "l"(src), "r"(bytes), "r"(bar) : "memory");
}
__device__ __forceinline__ void mbar_wait(uint32_t a, uint32_t parity) {
    asm volatile(
        "{\n\t.reg .pred P;\n"
        "W_%=:\n\t"
        "mbarrier.try_wait.parity.acquire.cta.shared::cta.b64 P, [%0], %1, 0x989680;\n\t"
        "@P bra D_%=;\n\t"
        "bra W_%=;\n"
        "D_%=:\n\t}"
        :: "r"(a), "r"(parity) : "memory");
}
// ------------------------------------------------------------------------

__global__ __launch_bounds__(256) void seg_k1(
    const float* __restrict__ O, const float* __restrict__ Lb,
    const void* __restrict__ lens, float* __restrict__ out)
{
    extern __shared__ __align__(16) unsigned char dsm[];
    float* bufO = (float*)dsm;                            // [NBUF][SROWS*Dc]
    unsigned long long* bar_s = (unsigned long long*)(dsm + OFF_BARS);
    int* s_flags = (int*)(dsm + OFF_FLAGS);               // [0]=elected [1]=final

    const int b   = blockIdx.y;
    const int c   = blockIdx.x;
    const int tid = threadIdx.x;
    const int col4 = tid & 31;   // d-group of 4 floats
    const int rg   = tid >> 5;   // 0..7; whole warp shares one row -> uniform masks

    const long long len  = read_len(lens, b);
    const long long half = len >> 1;
    const int t0 = c * ROWS;

    const char*   gO  = (const char*)(O + ((size_t)b * Tc + t0) * Dc);
    const float4* gL4 = (const float4*)(Lb + ((size_t)b * Tc + t0) * Dc);

    uint32_t bar[NBUF], dO[NBUF];
#pragma unroll
    for (int k = 0; k < NBUF; k++) {
        bar[k] = s2u(&bar_s[k]);
        dO[k]  = s2u(bufO + k * (SROWS * Dc));
    }

    if (tid == 0) {
#pragma unroll
        for (int k = 0; k < NBUF; k++) mbar_init(bar[k], 1);
    }
    __syncthreads();

    // Prologue: TMA prefetch O stages 0,1; LDG prefetch L stage 0.
    if (tid == 0) {
#pragma unroll
        for (int s = 0; s < 2; s++) {
            mbar_expect(bar[s], STAGE_BYTES);
            bulk_g2s(dO[s], gO + (size_t)s * STAGE_BYTES, STAGE_BYTES, bar[s]);
        }
    }
    float4 l0 = ldcs4(gL4 + (size_t)rg * 32 + col4);
    float4 l1 = ldcs4(gL4 + (size_t)(rg + 8) * 32 + col4);

    float4 mOF = {NEG_FILL, NEG_FILL, NEG_FILL, NEG_FILL};
    float4 mLF = mOF, mOS = mOF, mLS = mOF;
    float sum = 0.0f;

#pragma unroll
    for (int s = 0; s < NST; s++) {
        const int k = s % NBUF;
        mbar_wait(bar[k], (s / NBUF) & 1);

        // TMA early refill for O stage s+2 (buffer freed by stage s-1's sync).
        if (s + 2 < NST && tid == 0) {
            const int k2 = (s + 2) % NBUF;
            mbar_expect(bar[k2], STAGE_BYTES);
            bulk_g2s(dO[k2], gO + (size_t)(s + 2) * STAGE_BYTES, STAGE_BYTES, bar[k2]);
        }

        // LDG prefetch L for stage s+1 (latency overlaps this stage's compute).
        float4 nl0, nl1;
        if (s + 1 < NST) {
            const size_t base = (size_t)((s + 1) * SROWS) * 32;
            nl0 = ldcs4(gL4 + base + (size_t)rg * 32 + col4);
            nl1 = ldcs4(gL4 + base + (size_t)(rg + 8) * 32 + col4);
        }

        const float4* pO = (const float4*)(bufO + k * (SROWS * Dc));
        {
            const int r = rg;
            float4 o = pO[r * 32 + col4];
            float dx = o.x - l0.x, dy = o.y - l0.y, dz = o.z - l0.z, dw = o.w - l0.w;
            sum += dx * dx + dy * dy + dz * dz + dw * dw;
            long long t = (long long)(t0 + s * SROWS + r);
            if (t < half)      { mOF = max4(mOF, o); mLF = max4(mLF, l0); }
            else if (t < len)  { mOS = max4(mOS, o); mLS = max4(mLS, l0); }
        }
        {
            const int r = rg + 8;
            float4 o = pO[r * 32 + col4];
            float dx = o.x - l1.x, dy = o.y - l1.y, dz = o.z - l1.z, dw = o.w - l1.w;
            sum += dx * dx + dy * dy + dz * dz + dw * dw;
            long long t = (long long)(t0 + s * SROWS + r);
            if (t < half)      { mOF = max4(mOF, o); mLF = max4(mLF, l1); }
            else if (t < len)  { mOS = max4(mOS, o); mLS = max4(mLS, l1); }
        }
        __syncthreads();                           // buffer k free for reuse
        l0 = nl0; l1 = nl1;
    }

    // ---- intra-block reduction (reuse stage buffers as scratch) ----
    float4* red = (float4*)bufO;             // 16 KB at offset 0
    float*  ss  = (float*)(dsm + 16384);     // 256 floats
    red[(0 * 8 + rg) * 32 + col4] = mOF;
    red[(1 * 8 + rg) * 32 + col4] = mLF;
    red[(2 * 8 + rg) * 32 + col4] = mOS;
    red[(3 * 8 + rg) * 32 + col4] = mLS;
    ss[tid] = sum;
    __syncthreads();

    if (tid < 32) {
#pragma unroll
        for (int stat = 0; stat < 4; stat++) {
            float4 m = red[(stat * 8 + 0) * 32 + tid];
#pragma unroll
            for (int r = 1; r < 8; r++)
                m = max4(m, red[(stat * 8 + r) * 32 + tid]);
            ((float4*)g_part)[((b * CHUNKS + c) * 4 + stat) * 32 + tid] = m;
        }
    }
    for (int s = 128; s > 0; s >>= 1) {
        if (tid < s) ss[tid] += ss[tid + s];
        __syncthreads();
    }
    if (tid == 0) g_csum[b * CHUNKS + c] = ss[0];

    // Publish partials; elect the last chunk-block of this b.
    if (tid < 32) __threadfence();
    if (tid == 0) {
        unsigned old = atomicAdd(&g_bcount[b], 1u);
        s_flags[0] = (old == CHUNKS - 1) ? 1 : 0;
    }
    __syncthreads();
    if (!s_flags[0]) return;

    // ---- per-b reduction over 16 chunks (L2-hot, 32 KB) ----
    __threadfence();
    float* s1 = (float*)(dsm + 17408);   // 128 floats
    float* s2 = (float*)(dsm + 17920);   // 128 floats
    if (tid < 128) {
        const int d = tid;
        float r0 = NEG_FILL, r1 = NEG_FILL, r2 = NEG_FILL, r3 = NEG_FILL;
#pragma unroll
        for (int cc = 0; cc < CHUNKS; cc++) {
            const float* p = g_part + (size_t)((b * CHUNKS + cc) * 4) * Dc;
            r0 = fmaxf(r0, p[0 * Dc + d]);
            r1 = fmaxf(r1, p[1 * Dc + d]);
            r2 = fmaxf(r2, p[2 * Dc + d]);
            r3 = fmaxf(r3, p[3 * Dc + d]);
        }
        float d1 = r0 - r1;   // empty segment: (-1e30)-(-1e30)=0, matches reference
        float d2 = r2 - r3;
        s1[d] = d1 * d1;
        s2[d] = d2 * d2;
    }
    ss[tid] = (tid < CHUNKS) ? g_csum[b * CHUNKS + tid] : 0.0f;
    __syncthreads();
    for (int s = 64; s > 0; s >>= 1) {
        if (tid < s) {
            s1[tid] += s1[tid + s];
            s2[tid] += s2[tid + s];
            ss[tid] += ss[tid + s];
        }
        __syncthreads();
    }

    if (tid == 0) {
        float valid = (len >= 2) ? 1.0f : 0.0f;
        g_bres1[b] = valid * (s1[0] / (float)Dc);
        g_bres2[b] = valid * (s2[0] / (float)Dc);
        g_bsum[b]  = ss[0];
        g_bcount[b] = 0;                // reset for next graph replay
        __threadfence();
        unsigned old = atomicAdd(&g_count, 1u);
        s_flags[1] = (old == Bc - 1) ? 1 : 0;
    }
    __syncthreads();
    if (!s_flags[1]) return;

    // ---- global finalizer: warp 0 reduces 32 per-b results ----
    __threadfence();
    if (tid < 32) {
        double s = (double)g_bsum[tid];
        float r1 = g_bres1[tid];
        float r2 = g_bres2[tid];
#pragma unroll
        for (int o = 16; o > 0; o >>= 1) {
            s  += __shfl_down_sync(0xFFFFFFFFu, s,  o);
            r1 += __shfl_down_sync(0xFFFFFFFFu, r1, o);
            r2 += __shfl_down_sync(0xFFFFFFFFu, r2, o);
        }
        if (tid == 0) {
            g_count = 0;                // reset for next graph replay
            double base = s / (double)((size_t)Bc * Tc * Dc);
            out[0] = (float)(base + (double)ALPHA *
                             (((double)r1 + (double)r2) / (double)Bc));
        }
    }
}

extern "C" void kernel_launch(void* const* d_in, const int* in_sizes, int n_in,
                              void* d_out, int out_size)
{
    const float* outputs = (const float*)d_in[0];
    const float* labels  = (const float*)d_in[1];
    const void*  lens    = d_in[2];
    float* out = (float*)d_out;

    cudaFuncSetAttribute(seg_k1, cudaFuncAttributeMaxDynamicSharedMemorySize, SMEM_BYTES);
    dim3 g1(CHUNKS, Bc);
    seg_k1<<<g1, 256, SMEM_BYTES>>>(outputs, labels, lens, out);
}